// round 2
// baseline (speedup 1.0000x reference)
#include <cuda_runtime.h>
#include <math.h>

#define LSEQ 4096      // L = 16*16*16
#define NSq  8         // 4 parts * B=2 sequences
#define DI   128       // d_inner
#define DST  16        // d_state
#define NCHK 64        // scan chunks
#define CLEN 64        // chunk length
#define NCHAN (NSq*DI*DST)   // 16384 channels

// ---------------- static device scratch ----------------
__device__ float g_parts[NSq*LSEQ*64];
__device__ float g_uraw [NSq*LSEQ*DI];
__device__ float g_zbuf [NSq*LSEQ*DI];
__device__ float g_ubuf [NSq*LSEQ*DI];
__device__ float g_dt   [NSq*LSEQ*DI];
__device__ float g_Bm   [NSq*LSEQ*DST];
__device__ float g_Cm   [NSq*LSEQ*DST];
__device__ float g_Ap   [NCHK*NCHAN];
__device__ float g_Bp   [NCHK*NCHAN];
__device__ float g_Hc   [NCHK*NCHAN];
__device__ float g_xm   [2*LSEQ*256];
__device__ int   g_fast;

// ---------------- K0: detect A[d][k] == -(k+1) ----------------
__global__ void k0_check(const float* __restrict__ A_log) {
    __shared__ int ok;
    if (threadIdx.x == 0) ok = 1;
    __syncthreads();
    for (int i = threadIdx.x; i < DI*DST; i += blockDim.x) {
        int k = i & 15;
        float a = __expf(A_log[i]);
        if (fabsf(a - (float)(k + 1)) > 1e-3f * (float)(k + 1)) atomicAnd(&ok, 0);
    }
    __syncthreads();
    if (threadIdx.x == 0) g_fast = ok;
}

// ---------------- K1: LayerNorm + parts + in_proj ----------------
// grid (L/32, B), 256 threads
__global__ void __launch_bounds__(256)
k1_ln_inproj(const float* __restrict__ x, const float* __restrict__ lng,
             const float* __restrict__ lnb, const float* __restrict__ W) {
    extern __shared__ float sm[];
    float* xs  = sm;             // 32 x 257
    float* ws  = xs + 32*257;    // 64 x 260  (in_proj_w transposed [d][e])
    float* gs  = ws + 64*260;    // 256
    float* bs  = gs + 256;       // 256
    float* mus = bs + 256;       // 32
    float* rss = mus + 32;       // 32

    const int tid = threadIdx.x;
    const int b   = blockIdx.y;
    const int l0  = blockIdx.x * 32;

    #pragma unroll 4
    for (int i = 0; i < 64; i++) {            // W (256,64) -> ws[d][e]
        int idx = i*256 + tid;
        int e = idx >> 6, d = idx & 63;
        ws[d*260 + e] = W[e*64 + d];
    }
    gs[tid] = lng[tid]; bs[tid] = lnb[tid];

    #pragma unroll 4
    for (int i = 0; i < 32; i++) {            // x tile -> xs[l][c]
        int idx = i*256 + tid;
        int c = idx >> 5, ll = idx & 31;
        xs[ll*257 + c] = x[(b*256 + c)*LSEQ + l0 + ll];
    }
    __syncthreads();

    const int w = tid >> 5, lane = tid & 31;
    for (int i = 0; i < 4; i++) {             // LN stats: 8 warps x 4 rows
        int ll = w + i*8;
        float s = 0.f, s2 = 0.f;
        #pragma unroll
        for (int j = 0; j < 8; j++) {
            float v = xs[ll*257 + lane + j*32];
            s += v; s2 += v*v;
        }
        #pragma unroll
        for (int o = 16; o > 0; o >>= 1) {
            s  += __shfl_xor_sync(0xffffffffu, s,  o);
            s2 += __shfl_xor_sync(0xffffffffu, s2, o);
        }
        if (lane == 0) {
            float mu = s * (1.f/256.f);
            mus[ll] = mu;
            rss[ll] = rsqrtf(s2 * (1.f/256.f) - mu*mu + 1e-5f);
        }
    }
    __syncthreads();

    for (int ll = 0; ll < 32; ll++) {         // normalize + write parts
        int c = tid;
        float v = (xs[ll*257 + c] - mus[ll]) * rss[ll] * gs[c] + bs[c];
        xs[ll*257 + c] = v;
        int p = c >> 6, cq = c & 63;
        g_parts[((p*2 + b)*LSEQ + l0 + ll)*64 + cq] = v;
    }
    __syncthreads();

    // in_proj: thread = (te, tl); e = te*4+i, l = tl*8+j
    const int te = tid >> 2, tl = tid & 3;
    for (int p = 0; p < 4; p++) {
        float acc0[8], acc1[8], acc2[8], acc3[8];
        #pragma unroll
        for (int j = 0; j < 8; j++) { acc0[j]=0.f; acc1[j]=0.f; acc2[j]=0.f; acc3[j]=0.f; }
        #pragma unroll 4
        for (int d = 0; d < 64; d++) {
            float4 wv = *(const float4*)&ws[d*260 + te*4];
            float xv[8];
            #pragma unroll
            for (int j = 0; j < 8; j++) xv[j] = xs[(tl*8 + j)*257 + p*64 + d];
            #pragma unroll
            for (int j = 0; j < 8; j++) {
                acc0[j] += wv.x * xv[j];
                acc1[j] += wv.y * xv[j];
                acc2[j] += wv.z * xv[j];
                acc3[j] += wv.w * xv[j];
            }
        }
        const int s  = p*2 + b;
        const int e0 = te*4;
        #pragma unroll
        for (int j = 0; j < 8; j++) {
            int l = l0 + tl*8 + j;
            float4 val = make_float4(acc0[j], acc1[j], acc2[j], acc3[j]);
            if (e0 < 128) *(float4*)&g_uraw[(s*LSEQ + l)*128 + e0]       = val;
            else          *(float4*)&g_zbuf[(s*LSEQ + l)*128 + e0 - 128] = val;
        }
    }
}

// ---------------- K2: conv + silu + x_proj + dt_proj + softplus ----------------
// grid (L/32, NSq), 256 threads
__global__ void __launch_bounds__(256)
k2_conv(const float* __restrict__ cw, const float* __restrict__ cb,
        const float* __restrict__ xw, const float* __restrict__ dtw,
        const float* __restrict__ dtb) {
    extern __shared__ float sm[];
    float* ur   = sm;              // 35 x 130 (halo)
    float* us   = ur + 35*130;     // 32 x 130
    float* xws  = us + 32*130;     // 36 x 130
    float* dbc  = xws + 36*130;    // 32 x 40
    float* cws  = dbc + 32*40;     // 128 x 5
    float* dtws = cws + 128*5;     // 128 x 5
    float* cbs  = dtws + 128*5;    // 128
    float* dtbs = cbs + 128;       // 128

    const int tid = threadIdx.x;
    const int s   = blockIdx.y;
    const int l0  = blockIdx.x * 32;

    for (int i = tid; i < 128*4; i += 256) {
        int ch = i >> 2, j = i & 3;
        cws[ch*5 + j]  = cw[i];
        dtws[ch*5 + j] = dtw[i];
    }
    if (tid < 128) { cbs[tid] = cb[tid]; dtbs[tid] = dtb[tid]; }
    for (int i = tid; i < 36*128; i += 256) {
        int e = i >> 7, ch = i & 127;
        xws[e*130 + ch] = xw[i];
    }
    for (int i = tid; i < 35*128; i += 256) {
        int r = i >> 7, ch = i & 127;
        int l = l0 - 3 + r;
        ur[r*130 + ch] = (l >= 0) ? g_uraw[(s*LSEQ + l)*128 + ch] : 0.f;
    }
    __syncthreads();

    for (int i = tid; i < 32*128; i += 256) {     // conv + silu
        int ll = i >> 7, ch = i & 127;
        float a = cbs[ch];
        #pragma unroll
        for (int j = 0; j < 4; j++) a += cws[ch*5 + j] * ur[(ll + j)*130 + ch];
        float v = a / (1.f + __expf(-a));
        us[ll*130 + ch] = v;
        g_ubuf[(s*LSEQ + l0 + ll)*128 + ch] = v;
    }
    __syncthreads();

    for (int i = tid; i < 32*36; i += 256) {      // x_proj
        int ll = i / 36, e = i % 36;
        float a = 0.f;
        #pragma unroll 8
        for (int ch = 0; ch < 128; ch++) a += us[ll*130 + ch] * xws[e*130 + ch];
        dbc[ll*40 + e] = a;
    }
    __syncthreads();

    for (int i = tid; i < 32*16; i += 256) {      // write B, C
        int ll = i >> 4, k = i & 15;
        g_Bm[(s*LSEQ + l0 + ll)*16 + k] = dbc[ll*40 + 4 + k];
        g_Cm[(s*LSEQ + l0 + ll)*16 + k] = dbc[ll*40 + 20 + k];
    }
    for (int i = tid; i < 32*128; i += 256) {     // dt_proj + softplus
        int ll = i >> 7, d = i & 127;
        float a = dtbs[d];
        #pragma unroll
        for (int r = 0; r < 4; r++) a += dbc[ll*40 + r] * dtws[d*5 + r];
        float sp = (a > 20.f) ? a : log1pf(__expf(a));
        g_dt[(s*LSEQ + l0 + ll)*128 + d] = sp;
    }
}

// q[k] = p^(k+1)
__device__ __forceinline__ void pow_tree(float p, float* q) {
    float p2 = p*p, p4 = p2*p2, p8 = p4*p4;
    q[0]=p;        q[1]=p2;       q[2]=p2*p;     q[3]=p4;
    q[4]=p4*p;     q[5]=p4*p2;    q[6]=p4*q[2];  q[7]=p8;
    q[8]=p8*p;     q[9]=p8*p2;    q[10]=p8*q[2]; q[11]=p8*p4;
    q[12]=p8*q[4]; q[13]=p8*q[5]; q[14]=p8*q[6]; q[15]=p8*p8;
}

// ---------------- K3: scan pass 1 (chunk summaries) ----------------
// grid (NCHK, NSq), 128 threads
__global__ void __launch_bounds__(128)
k3_scan1(const float* __restrict__ A_log) {
    extern __shared__ float sm[];
    float* dts = sm;              // 64 x 130
    float* uts = dts + 64*130;    // 64 x 130
    float* Bsh = uts + 64*130;    // 64 x 17

    const int tid = threadIdx.x;
    const int s   = blockIdx.y;
    const int c   = blockIdx.x;
    const int l0  = c * CLEN;

    for (int l = 0; l < CLEN; l++) {
        dts[l*130 + tid] = g_dt  [(s*LSEQ + l0 + l)*128 + tid];
        uts[l*130 + tid] = g_ubuf[(s*LSEQ + l0 + l)*128 + tid];
    }
    for (int i = tid; i < CLEN*16; i += 128) {
        int l = i >> 4, k = i & 15;
        Bsh[l*17 + k] = g_Bm[(s*LSEQ + l0 + l)*16 + k];
    }
    const int fast = g_fast;
    float Areg[16];
    if (!fast) {
        #pragma unroll
        for (int k = 0; k < 16; k++) Areg[k] = -__expf(A_log[tid*16 + k]);
    }
    __syncthreads();

    float h[16];
    #pragma unroll
    for (int k = 0; k < 16; k++) h[k] = 0.f;
    const int ch = (s*128 + tid)*16;

    if (fast) {
        float P = 1.f;
        for (int l = 0; l < CLEN; l++) {
            float dt = dts[l*130 + tid];
            float du = dt * uts[l*130 + tid];
            float p  = __expf(-dt);
            P *= p;
            float q[16]; pow_tree(p, q);
            #pragma unroll
            for (int k = 0; k < 16; k++) h[k] = q[k]*h[k] + du*Bsh[l*17 + k];
        }
        float Q = P;
        #pragma unroll
        for (int k = 0; k < 16; k++) {
            g_Ap[c*NCHAN + ch + k] = Q;
            g_Bp[c*NCHAN + ch + k] = h[k];
            Q *= P;
        }
    } else {
        float ap[16];
        #pragma unroll
        for (int k = 0; k < 16; k++) ap[k] = 1.f;
        for (int l = 0; l < CLEN; l++) {
            float dt = dts[l*130 + tid];
            float du = dt * uts[l*130 + tid];
            #pragma unroll
            for (int k = 0; k < 16; k++) {
                float a = __expf(dt * Areg[k]);
                h[k]  = a*h[k] + du*Bsh[l*17 + k];
                ap[k] *= a;
            }
        }
        #pragma unroll
        for (int k = 0; k < 16; k++) {
            g_Ap[c*NCHAN + ch + k] = ap[k];
            g_Bp[c*NCHAN + ch + k] = h[k];
        }
    }
}

// ---------------- K3b: inter-chunk carry scan ----------------
__global__ void __launch_bounds__(256)
k3b_carry() {
    int ch = blockIdx.x*256 + threadIdx.x;
    float h = 0.f;
    #pragma unroll 4
    for (int c = 0; c < NCHK; c++) {
        g_Hc[c*NCHAN + ch] = h;
        h = g_Ap[c*NCHAN + ch]*h + g_Bp[c*NCHAN + ch];
    }
}

// ---------------- K4: scan pass 2 + gate + out_proj + skip ----------------
// grid (NCHK, NSq), 256 threads (scan on first 128)
__global__ void __launch_bounds__(256)
k4_scan2(const float* __restrict__ A_log, const float* __restrict__ Dp,
         const float* __restrict__ Wout, const float* __restrict__ skip) {
    extern __shared__ float sm[];
    float* dts = sm;              // 64 x 130 (becomes gated y after scan)
    float* uts = dts + 64*130;    // 64 x 130
    float* zs  = uts + 64*130;    // 64 x 130
    float* Bsh = zs + 64*130;     // 64 x 17
    float* Csh = Bsh + 64*17;     // 64 x 17
    float* wo  = Csh + 64*17;     // 128 x 66 (out_proj_w transposed [d][o])
    float* Ds  = wo + 128*66;     // 128

    const int tid = threadIdx.x;
    const int s   = blockIdx.y;
    const int c   = blockIdx.x;
    const int l0  = c * CLEN;

    for (int i = tid; i < 64*128; i += 256) {
        int l = i >> 7, d = i & 127;
        int g = (s*LSEQ + l0 + l)*128 + d;
        dts[l*130 + d] = g_dt[g];
        uts[l*130 + d] = g_ubuf[g];
        zs [l*130 + d] = g_zbuf[g];
    }
    for (int i = tid; i < 64*16; i += 256) {
        int l = i >> 4, k = i & 15;
        Bsh[l*17 + k] = g_Bm[(s*LSEQ + l0 + l)*16 + k];
        Csh[l*17 + k] = g_Cm[(s*LSEQ + l0 + l)*16 + k];
    }
    for (int i = tid; i < 64*128; i += 256) {
        int o = i >> 7, d = i & 127;
        wo[d*66 + o] = Wout[i];
    }
    if (tid < 128) Ds[tid] = Dp[tid];
    __syncthreads();

    if (tid < 128) {
        const int fast = g_fast;
        float Areg[16];
        if (!fast) {
            #pragma unroll
            for (int k = 0; k < 16; k++) Areg[k] = -__expf(A_log[tid*16 + k]);
        }
        float h[16];
        const int ch = (s*128 + tid)*16;
        #pragma unroll
        for (int k = 0; k < 16; k++) h[k] = g_Hc[c*NCHAN + ch + k];
        const float Dd = Ds[tid];

        if (fast) {
            for (int l = 0; l < CLEN; l++) {
                float dt = dts[l*130 + tid];
                float uu = uts[l*130 + tid];
                float du = dt * uu;
                float zv = zs[l*130 + tid];
                float p  = __expf(-dt);
                float q[16]; pow_tree(p, q);
                float y = Dd * uu;
                #pragma unroll
                for (int k = 0; k < 16; k++) {
                    h[k] = q[k]*h[k] + du*Bsh[l*17 + k];
                    y   += h[k]*Csh[l*17 + k];
                }
                float sg = 1.f / (1.f + __expf(-zv));
                dts[l*130 + tid] = y * zv * sg;
            }
        } else {
            for (int l = 0; l < CLEN; l++) {
                float dt = dts[l*130 + tid];
                float uu = uts[l*130 + tid];
                float du = dt * uu;
                float zv = zs[l*130 + tid];
                float y = Dd * uu;
                #pragma unroll
                for (int k = 0; k < 16; k++) {
                    float a = __expf(dt * Areg[k]);
                    h[k] = a*h[k] + du*Bsh[l*17 + k];
                    y   += h[k]*Csh[l*17 + k];
                }
                float sg = 1.f / (1.f + __expf(-zv));
                dts[l*130 + tid] = y * zv * sg;
            }
        }
    }
    __syncthreads();

    // out_proj (64 o x 128 d) + skip -> g_xm ; 256 threads
    const float sk = skip[0];
    const int og = tid & 31;   // o pair
    const int lg = tid >> 5;   // 8 l's each
    float acc0[8], acc1[8];
    #pragma unroll
    for (int j = 0; j < 8; j++) { acc0[j] = 0.f; acc1[j] = 0.f; }
    #pragma unroll 2
    for (int d = 0; d < 128; d++) {
        float2 wv = *(const float2*)&wo[d*66 + og*2];
        #pragma unroll
        for (int j = 0; j < 8; j++) {
            float yv = dts[(lg*8 + j)*130 + d];
            acc0[j] += wv.x * yv;
            acc1[j] += wv.y * yv;
        }
    }
    const int p = s >> 1, b = s & 1;
    const int o0 = og*2;
    #pragma unroll
    for (int j = 0; j < 8; j++) {
        int l = l0 + lg*8 + j;
        float2 pv = *(const float2*)&g_parts[(s*LSEQ + l)*64 + o0];
        float2 ov;
        ov.x = acc0[j] + sk*pv.x;
        ov.y = acc1[j] + sk*pv.y;
        *(float2*)&g_xm[(b*LSEQ + l)*256 + p*64 + o0] = ov;
    }
}

// ---------------- K5: final LN + 256x256 proj + bias + transpose ----------------
// grid (L/32, B), 256 threads
__global__ void __launch_bounds__(256)
k5_ln_proj(const float* __restrict__ lng, const float* __restrict__ lnb,
           const float* __restrict__ Wp, const float* __restrict__ bp,
           float* __restrict__ out) {
    extern __shared__ float sm[];
    float* xs  = sm;             // 32 x 257
    float* wt  = xs + 32*257;    // 64 x 264 (chunk of proj_w transposed [c'][o]); reused as ys 256x33
    float* gs  = wt + 64*264;    // 256
    float* bs  = gs + 256;       // 256
    float* mus = bs + 256;       // 32
    float* rss = mus + 32;       // 32

    const int tid = threadIdx.x;
    const int b   = blockIdx.y;
    const int l0  = blockIdx.x * 32;

    gs[tid] = lng[tid]; bs[tid] = lnb[tid];
    #pragma unroll 4
    for (int i = 0; i < 32; i++)
        xs[i*257 + tid] = g_xm[(b*LSEQ + l0 + i)*256 + tid];
    __syncthreads();

    const int w = tid >> 5, lane = tid & 31;
    for (int i = 0; i < 4; i++) {
        int ll = w + i*8;
        float s = 0.f, s2 = 0.f;
        #pragma unroll
        for (int j = 0; j < 8; j++) {
            float v = xs[ll*257 + lane + j*32];
            s += v; s2 += v*v;
        }
        #pragma unroll
        for (int o = 16; o > 0; o >>= 1) {
            s  += __shfl_xor_sync(0xffffffffu, s,  o);
            s2 += __shfl_xor_sync(0xffffffffu, s2, o);
        }
        if (lane == 0) {
            float mu = s * (1.f/256.f);
            mus[ll] = mu;
            rss[ll] = rsqrtf(s2 * (1.f/256.f) - mu*mu + 1e-5f);
        }
    }
    __syncthreads();
    for (int ll = 0; ll < 32; ll++) {
        int c = tid;
        xs[ll*257 + c] = (xs[ll*257 + c] - mus[ll]) * rss[ll] * gs[c] + bs[c];
    }

    const int to = tid >> 2, tl = tid & 3;
    const int o0 = to*4;
    float4 pb = *(const float4*)&bp[o0];
    float acc0[8], acc1[8], acc2[8], acc3[8];
    #pragma unroll
    for (int j = 0; j < 8; j++) { acc0[j]=pb.x; acc1[j]=pb.y; acc2[j]=pb.z; acc3[j]=pb.w; }

    for (int c0 = 0; c0 < 256; c0 += 64) {
        __syncthreads();
        #pragma unroll 4
        for (int i = 0; i < 64; i++) {        // proj_w chunk -> wt[c'][o]
            int idx = i*256 + tid;
            int o = idx >> 6, cc = idx & 63;
            wt[cc*264 + o] = Wp[o*256 + c0 + cc];
        }
        __syncthreads();
        #pragma unroll 4
        for (int cc = 0; cc < 64; cc++) {
            float4 wv = *(const float4*)&wt[cc*264 + o0];
            float xv[8];
            #pragma unroll
            for (int j = 0; j < 8; j++) xv[j] = xs[(tl*8 + j)*257 + c0 + cc];
            #pragma unroll
            for (int j = 0; j < 8; j++) {
                acc0[j] += wv.x * xv[j];
                acc1[j] += wv.y * xv[j];
                acc2[j] += wv.z * xv[j];
                acc3[j] += wv.w * xv[j];
            }
        }
    }
    __syncthreads();

    float* ys = wt;   // 256 x 33 overlay
    #pragma unroll
    for (int j = 0; j < 8; j++) {
        int l = tl*8 + j;
        ys[(o0+0)*33 + l] = acc0[j];
        ys[(o0+1)*33 + l] = acc1[j];
        ys[(o0+2)*33 + l] = acc2[j];
        ys[(o0+3)*33 + l] = acc3[j];
    }
    __syncthreads();
    #pragma unroll 4
    for (int i = tid; i < 256*32; i += 256) {
        int o = i >> 5, l = i & 31;
        out[(b*256 + o)*LSEQ + l0 + l] = ys[o*33 + l];
    }
}

// ---------------- launch ----------------
extern "C" void kernel_launch(void* const* d_in, const int* in_sizes, int n_in,
                              void* d_out, int out_size) {
    const float* x     = (const float*)d_in[0];
    const float* ln_g  = (const float*)d_in[1];
    const float* ln_b  = (const float*)d_in[2];
    const float* skip  = (const float*)d_in[3];
    const float* inw   = (const float*)d_in[4];
    const float* convw = (const float*)d_in[5];
    const float* convb = (const float*)d_in[6];
    const float* xprojw= (const float*)d_in[7];
    const float* dtw   = (const float*)d_in[8];
    const float* dtb   = (const float*)d_in[9];
    const float* A_log = (const float*)d_in[10];
    const float* Dp    = (const float*)d_in[11];
    const float* outw  = (const float*)d_in[12];
    const float* projw = (const float*)d_in[13];
    const float* projb = (const float*)d_in[14];
    float* out = (float*)d_out;

    const int SM1 = (32*257 + 64*260 + 256+256+32+32) * 4;
    const int SM2 = (35*130 + 32*130 + 36*130 + 32*40 + 128*5 + 128*5 + 128 + 128) * 4;
    const int SM3 = (64*130*2 + 64*17) * 4;
    const int SM4 = (64*130*3 + 64*17*2 + 128*66 + 128) * 4;
    const int SM5 = (32*257 + 64*264 + 256+256+32+32) * 4;

    cudaFuncSetAttribute(k1_ln_inproj, cudaFuncAttributeMaxDynamicSharedMemorySize, SM1);
    cudaFuncSetAttribute(k2_conv,      cudaFuncAttributeMaxDynamicSharedMemorySize, SM2);
    cudaFuncSetAttribute(k3_scan1,     cudaFuncAttributeMaxDynamicSharedMemorySize, SM3);
    cudaFuncSetAttribute(k4_scan2,     cudaFuncAttributeMaxDynamicSharedMemorySize, SM4);
    cudaFuncSetAttribute(k5_ln_proj,   cudaFuncAttributeMaxDynamicSharedMemorySize, SM5);

    k0_check<<<1, 256>>>(A_log);
    k1_ln_inproj<<<dim3(LSEQ/32, 2), 256, SM1>>>(x, ln_g, ln_b, inw);
    k2_conv<<<dim3(LSEQ/32, NSq), 256, SM2>>>(convw, convb, xprojw, dtw, dtb);
    k3_scan1<<<dim3(NCHK, NSq), 128, SM3>>>(A_log);
    k3b_carry<<<NCHAN/256, 256>>>();
    k4_scan2<<<dim3(NCHK, NSq), 256, SM4>>>(A_log, Dp, outw, skip);
    k5_ln_proj<<<dim3(LSEQ/32, 2), 256, SM5>>>(ln_g, ln_b, projw, projb, out);
}